// round 2
// baseline (speedup 1.0000x reference)
#include <cuda_runtime.h>
#include <math.h>

#define NSZ 1024
#define BM 128
#define BN 128
#define BK 16
#define TM 8
#define TN 8
#define NTHREADS 256

// Scratch (static device arrays are allowed; no runtime allocation).
__device__ float g_P[8u * 1024u * 1024u];   // L_g @ in_g   per gate
__device__ float g_G[4u * 1024u * 1024u];   // activated gates i, f, g, o

struct ParamsA { const float* L[8]; const float* X[8]; };
struct ParamsB { const float* R[8]; const float* Bi[8]; };

__device__ __forceinline__ float sigmoidf_fast(float s) {
    return 1.0f / (1.0f + __expf(-s));
}

// Accumulate one 1024-K GEMM tile contribution into acc.
// A: row-major [1024 x 1024], B: row-major [1024 x 1024].
__device__ __forceinline__ void gemm_accum(
    const float* __restrict__ A, const float* __restrict__ B,
    float (&acc)[TM][TN], float* As, float* Bs,
    int rowTile, int colTile, int tid)
{
    const int tr = (tid >> 4) * TM;   // 0..120, 16B aligned
    const int tc = (tid & 15) * TN;

    for (int k0 = 0; k0 < NSZ; k0 += BK) {
        // Load A tile [BM x BK], store transposed As[BK][BM]
        #pragma unroll
        for (int i = 0; i < 2; i++) {
            int f  = tid + i * NTHREADS;      // float4 index 0..511, coalesced
            int r  = f >> 2;                  // 0..127
            int c4 = (f & 3) << 2;            // 0,4,8,12
            float4 v = *(const float4*)(A + (size_t)(rowTile + r) * NSZ + k0 + c4);
            As[(c4 + 0) * BM + r] = v.x;
            As[(c4 + 1) * BM + r] = v.y;
            As[(c4 + 2) * BM + r] = v.z;
            As[(c4 + 3) * BM + r] = v.w;
        }
        // Load B tile [BK x BN] direct
        #pragma unroll
        for (int i = 0; i < 2; i++) {
            int f  = tid + i * NTHREADS;
            int r  = f >> 5;                  // 0..15
            int cc = (f & 31) << 2;           // 0..124
            *(float4*)(Bs + r * BN + cc) =
                *(const float4*)(B + (size_t)(k0 + r) * NSZ + colTile + cc);
        }
        __syncthreads();

        #pragma unroll
        for (int k = 0; k < BK; k++) {
            float a[TM], bb[TN];
            *(float4*)&a[0]  = *(float4*)(As + k * BM + tr);
            *(float4*)&a[4]  = *(float4*)(As + k * BM + tr + 4);
            *(float4*)&bb[0] = *(float4*)(Bs + k * BN + tc);
            *(float4*)&bb[4] = *(float4*)(Bs + k * BN + tc + 4);
            #pragma unroll
            for (int m = 0; m < TM; m++)
                #pragma unroll
                for (int n = 0; n < TN; n++)
                    acc[m][n] = fmaf(a[m], bb[n], acc[m][n]);
        }
        __syncthreads();
    }
}

// Kernel A: P_g = L_g @ X_g   (z = gate 0..7)
__global__ void __launch_bounds__(NTHREADS, 2)
kernelA(ParamsA p)
{
    __shared__ float As[BK * BM];
    __shared__ float Bs[BK * BN];
    const int g   = blockIdx.z;
    const int tid = threadIdx.x;

    float acc[TM][TN];
    #pragma unroll
    for (int m = 0; m < TM; m++)
        #pragma unroll
        for (int n = 0; n < TN; n++) acc[m][n] = 0.0f;

    gemm_accum(p.L[g], p.X[g], acc, As, Bs,
               blockIdx.y * BM, blockIdx.x * BN, tid);

    float* out = g_P + (size_t)g * (NSZ * NSZ);
    const int row = blockIdx.y * BM + (tid >> 4) * TM;
    const int col = blockIdx.x * BN + (tid & 15) * TN;
    #pragma unroll
    for (int m = 0; m < TM; m++) {
        *(float4*)(out + (size_t)(row + m) * NSZ + col) =
            make_float4(acc[m][0], acc[m][1], acc[m][2], acc[m][3]);
        *(float4*)(out + (size_t)(row + m) * NSZ + col + 4) =
            make_float4(acc[m][4], acc[m][5], acc[m][6], acc[m][7]);
    }
}

// Kernel B: S_p = P_{2p} @ R_{2p} + P_{2p+1} @ R_{2p+1} + b_{2p} + b_{2p+1}
// then activation (tanh for p==2, sigmoid otherwise) into g_G.  (z = pair 0..3)
__global__ void __launch_bounds__(NTHREADS, 2)
kernelB(ParamsB p)
{
    __shared__ float As[BK * BM];
    __shared__ float Bs[BK * BN];
    const int pr  = blockIdx.z;   // 0:i 1:f 2:g 3:o
    const int tid = threadIdx.x;

    float acc[TM][TN];
    #pragma unroll
    for (int m = 0; m < TM; m++)
        #pragma unroll
        for (int n = 0; n < TN; n++) acc[m][n] = 0.0f;

    const int rowTile = blockIdx.y * BM;
    const int colTile = blockIdx.x * BN;

    gemm_accum(g_P + (size_t)(2 * pr) * (NSZ * NSZ),     p.R[2 * pr],
               acc, As, Bs, rowTile, colTile, tid);
    gemm_accum(g_P + (size_t)(2 * pr + 1) * (NSZ * NSZ), p.R[2 * pr + 1],
               acc, As, Bs, rowTile, colTile, tid);

    const float* __restrict__ b0 = p.Bi[2 * pr];
    const float* __restrict__ b1 = p.Bi[2 * pr + 1];
    float* out = g_G + (size_t)pr * (NSZ * NSZ);

    const int row = rowTile + (tid >> 4) * TM;
    const int col = colTile + (tid & 15) * TN;
    const bool is_tanh = (pr == 2);

    #pragma unroll
    for (int m = 0; m < TM; m++) {
        const size_t base = (size_t)(row + m) * NSZ + col;
        #pragma unroll
        for (int q = 0; q < 2; q++) {
            float4 v0 = *(const float4*)(b0 + base + 4 * q);
            float4 v1 = *(const float4*)(b1 + base + 4 * q);
            float s0 = acc[m][4 * q + 0] + v0.x + v1.x;
            float s1 = acc[m][4 * q + 1] + v0.y + v1.y;
            float s2 = acc[m][4 * q + 2] + v0.z + v1.z;
            float s3 = acc[m][4 * q + 3] + v0.w + v1.w;
            float4 r;
            if (is_tanh) {
                r.x = tanhf(s0); r.y = tanhf(s1); r.z = tanhf(s2); r.w = tanhf(s3);
            } else {
                r.x = sigmoidf_fast(s0); r.y = sigmoidf_fast(s1);
                r.z = sigmoidf_fast(s2); r.w = sigmoidf_fast(s3);
            }
            *(float4*)(out + base + 4 * q) = r;
        }
    }
}

// Kernel C: c' = f*c + i*g ; h' = o*tanh(c') ; out = [h' | c']
__global__ void __launch_bounds__(256)
kernelC(const float* __restrict__ c, float* __restrict__ out)
{
    const int idx = blockIdx.x * blockDim.x + threadIdx.x;   // float4 index
    const int n4  = (NSZ * NSZ) / 4;
    if (idx >= n4) return;

    const float4* Gi = (const float4*)g_G;
    const float4* Gf = (const float4*)(g_G + 1 * (size_t)(NSZ * NSZ));
    const float4* Gg = (const float4*)(g_G + 2 * (size_t)(NSZ * NSZ));
    const float4* Go = (const float4*)(g_G + 3 * (size_t)(NSZ * NSZ));
    const float4* C  = (const float4*)c;

    float4 vi = Gi[idx], vf = Gf[idx], vg = Gg[idx], vo = Go[idx], vc = C[idx];

    float4 cn, hn;
    cn.x = vf.x * vc.x + vi.x * vg.x;
    cn.y = vf.y * vc.y + vi.y * vg.y;
    cn.z = vf.z * vc.z + vi.z * vg.z;
    cn.w = vf.w * vc.w + vi.w * vg.w;
    hn.x = vo.x * tanhf(cn.x);
    hn.y = vo.y * tanhf(cn.y);
    hn.z = vo.z * tanhf(cn.z);
    hn.w = vo.w * tanhf(cn.w);

    float4* outH = (float4*)out;
    float4* outC = (float4*)(out + (size_t)(NSZ * NSZ));
    outH[idx] = hn;
    outC[idx] = cn;
}

extern "C" void kernel_launch(void* const* d_in, const int* in_sizes, int n_in,
                              void* d_out, int out_size)
{
    (void)in_sizes; (void)n_in; (void)out_size;

    const float* x = (const float*)d_in[0];
    const float* h = (const float*)d_in[1];
    const float* c = (const float*)d_in[2];

    ParamsA pa;
    ParamsB pb;
    for (int g = 0; g < 8; g++) {
        pa.L[g]  = (const float*)d_in[3 + 3 * g];     // L_g
        pb.R[g]  = (const float*)d_in[4 + 3 * g];     // R_g
        pb.Bi[g] = (const float*)d_in[5 + 3 * g];     // b_g
        pa.X[g]  = (g & 1) ? h : x;                   // ii,if,ig,io use x; h* use h
    }

    dim3 block(NTHREADS);
    dim3 gridA(NSZ / BN, NSZ / BM, 8);
    dim3 gridB(NSZ / BN, NSZ / BM, 4);

    kernelA<<<gridA, block>>>(pa);
    kernelB<<<gridB, block>>>(pb);

    int n4 = (NSZ * NSZ) / 4;
    kernelC<<<(n4 + 255) / 256, 256>>>(c, (float*)d_out);
}

// round 4
// speedup vs baseline: 2.1711x; 2.1711x over previous
#include <cuda_runtime.h>
#include <cuda_bf16.h>
#include <cstdint>
#include <math.h>

#define NSZ 1024

// ---------------- scratch (static device globals; no runtime alloc) --------
__device__ __align__(16) __nv_bfloat16 g_Lh[8u << 20];
__device__ __align__(16) __nv_bfloat16 g_Ll[8u << 20];
__device__ __align__(16) __nv_bfloat16 g_XTh[2u << 20];
__device__ __align__(16) __nv_bfloat16 g_XTl[2u << 20];
__device__ __align__(16) __nv_bfloat16 g_RTh[8u << 20];
__device__ __align__(16) __nv_bfloat16 g_RTl[8u << 20];
__device__ __align__(16) __nv_bfloat16 g_Ph[8u << 20];
__device__ __align__(16) __nv_bfloat16 g_Pl[8u << 20];
__device__ __align__(16) float g_G[4u << 20];

// ---------------- SMEM stage layout ----------------------------------------
#define OFF_AL 8192
#define OFF_BH 16384
#define OFF_BL 24576
#define STAGE_BYTES 32768
#define NSTAGES 4
#define SMEM_TOTAL (NSTAGES * STAGE_BYTES)   // 128 KB

// ---------------- PTX helpers (all baseline sm_80-level) --------------------
__device__ __forceinline__ uint32_t smem_u32(const void* p) {
    uint32_t a;
    asm("{ .reg .u64 t; cvta.to.shared.u64 t, %1; cvt.u32.u64 %0, t; }"
        : "=r"(a) : "l"(p));
    return a;
}
__device__ __forceinline__ void cp16(uint32_t smem, const void* g) {
    asm volatile("cp.async.cg.shared.global [%0], [%1], 16;"
                 :: "r"(smem), "l"(g));
}
__device__ __forceinline__ void cp_commit() {
    asm volatile("cp.async.commit_group;" ::: "memory");
}
__device__ __forceinline__ void cp_wait2() {
    asm volatile("cp.async.wait_group 2;" ::: "memory");
}
__device__ __forceinline__ void ldsm_x4(uint32_t (&r)[4], uint32_t addr) {
    asm volatile("ldmatrix.sync.aligned.m8n8.x4.shared.b16 {%0,%1,%2,%3}, [%4];"
                 : "=r"(r[0]), "=r"(r[1]), "=r"(r[2]), "=r"(r[3]) : "r"(addr));
}
__device__ __forceinline__ void mma16816(float (&d)[4], const uint32_t (&a)[4],
                                         uint32_t b0, uint32_t b1) {
    asm volatile("mma.sync.aligned.m16n8k16.row.col.f32.bf16.bf16.f32 "
                 "{%0,%1,%2,%3}, {%4,%5,%6,%7}, {%8,%9}, {%0,%1,%2,%3};"
                 : "+f"(d[0]), "+f"(d[1]), "+f"(d[2]), "+f"(d[3])
                 : "r"(a[0]), "r"(a[1]), "r"(a[2]), "r"(a[3]), "r"(b0), "r"(b1));
}

// swizzle: 16B chunk j within 64B row r -> j ^ ((r>>1)&3)
__device__ __forceinline__ uint32_t sw_off(int r, int j) {
    return (uint32_t)(r * 64 + ((j ^ ((r >> 1) & 3)) << 4));
}

// load one [128 rows x 32 k] bf16 tile into swizzled SMEM via cp.async
__device__ __forceinline__ void issue_mat(const __nv_bfloat16* __restrict__ src,
                                          int row0, int k0, uint32_t dst, int tid) {
    #pragma unroll
    for (int i = 0; i < 2; i++) {
        int f = tid + i * 256;
        int r = f >> 2;
        int j = f & 3;
        cp16(dst + sw_off(r, j), src + (size_t)(row0 + r) * NSZ + k0 + j * 8);
    }
}

__device__ __forceinline__ void issue_stage(uint32_t sb, int buf,
    const __nv_bfloat16* Ah, const __nv_bfloat16* Al,
    const __nv_bfloat16* Bh, const __nv_bfloat16* Bl,
    int rowTile, int colTile, int k0, int tid)
{
    uint32_t base = sb + buf * STAGE_BYTES;
    issue_mat(Ah, rowTile, k0, base,          tid);
    issue_mat(Al, rowTile, k0, base + OFF_AL, tid);
    issue_mat(Bh, colTile, k0, base + OFF_BH, tid);
    issue_mat(Bl, colTile, k0, base + OFF_BL, tid);
    cp_commit();
}

// ---------------- split-bf16 GEMM mainloop ----------------------------------
// acc += Ah*Bh + Ah*Bl + Al*Bh   (K = 1024 per half, nhalf halves)
__device__ __forceinline__ void mainloop(
    uint32_t sb, int tid, int nhalf,
    const __nv_bfloat16* const* Ah, const __nv_bfloat16* const* Al,
    const __nv_bfloat16* const* Bh, const __nv_bfloat16* const* Bl,
    int rowTile, int colTile, float (&acc)[4][4][4])
{
    const int lane = tid & 31;
    const int wid  = tid >> 5;
    const int wm   = wid >> 2;       // 0..1  (64 rows)
    const int wn   = wid & 3;        // 0..3  (32 cols)

    // precompute ldmatrix lane offsets (relative to stage base)
    uint32_t aOff[2][4], bOff[2][2];
    #pragma unroll
    for (int ks = 0; ks < 2; ks++) {
        #pragma unroll
        for (int mt = 0; mt < 4; mt++) {
            int r = wm * 64 + mt * 16 + (lane & 15);
            int j = ks * 2 + (lane >> 4);
            aOff[ks][mt] = sw_off(r, j);
        }
        #pragma unroll
        for (int bp = 0; bp < 2; bp++) {
            int r = wn * 32 + bp * 16 + ((lane >> 4) * 8) + (lane & 7);
            int j = ks * 2 + ((lane >> 3) & 1);
            bOff[ks][bp] = OFF_BH + sw_off(r, j);
        }
    }

    const int NS = 32 * nhalf;

    // prologue: 3 stages in flight
    #pragma unroll
    for (int s = 0; s < 3; s++)
        issue_stage(sb, s, Ah[0], Al[0], Bh[0], Bl[0],
                    rowTile, colTile, s * 32, tid);

    #pragma unroll 1
    for (int s = 0; s < NS; s++) {
        cp_wait2();
        __syncthreads();
        int sn = s + 3;
        if (sn < NS) {
            int hf = sn >> 5;
            issue_stage(sb, sn & 3, Ah[hf], Al[hf], Bh[hf], Bl[hf],
                        rowTile, colTile, (sn & 31) * 32, tid);
        } else {
            cp_commit();   // keep group numbering aligned
        }

        uint32_t base = sb + (s & 3) * STAGE_BYTES;
        #pragma unroll
        for (int ks = 0; ks < 2; ks++) {
            uint32_t Af[4][4], Lf[4][4], Bf[2][4];
            #pragma unroll
            for (int mt = 0; mt < 4; mt++) ldsm_x4(Af[mt], base + aOff[ks][mt]);
            #pragma unroll
            for (int mt = 0; mt < 4; mt++) ldsm_x4(Lf[mt], base + OFF_AL + aOff[ks][mt]);
            #pragma unroll
            for (int bp = 0; bp < 2; bp++) ldsm_x4(Bf[bp], base + bOff[ks][bp]);

            // pass hh
            #pragma unroll
            for (int mt = 0; mt < 4; mt++)
                #pragma unroll
                for (int nt = 0; nt < 4; nt++)
                    mma16816(acc[mt][nt], Af[mt],
                             Bf[nt >> 1][(nt & 1) * 2], Bf[nt >> 1][(nt & 1) * 2 + 1]);
            // pass lh (A-lo x B-hi)
            #pragma unroll
            for (int mt = 0; mt < 4; mt++)
                #pragma unroll
                for (int nt = 0; nt < 4; nt++)
                    mma16816(acc[mt][nt], Lf[mt],
                             Bf[nt >> 1][(nt & 1) * 2], Bf[nt >> 1][(nt & 1) * 2 + 1]);
            // load B-lo, pass hl (A-hi x B-lo)
            #pragma unroll
            for (int bp = 0; bp < 2; bp++) ldsm_x4(Bf[bp], base + 8192 + bOff[ks][bp]);
            #pragma unroll
            for (int mt = 0; mt < 4; mt++)
                #pragma unroll
                for (int nt = 0; nt < 4; nt++)
                    mma16816(acc[mt][nt], Af[mt],
                             Bf[nt >> 1][(nt & 1) * 2], Bf[nt >> 1][(nt & 1) * 2 + 1]);
        }
    }
}

// ---------------- Kernel: phase 1  P_g = L_g @ X_g --------------------------
__global__ void __launch_bounds__(256, 1)
gemm1()
{
    extern __shared__ char smem[];
    const uint32_t sb = smem_u32(smem);
    const int tid = threadIdx.x;
    const int gate = blockIdx.z;
    const int rowTile = blockIdx.y * 128, colTile = blockIdx.x * 128;

    float acc[4][4][4];
    #pragma unroll
    for (int a = 0; a < 4; a++)
        #pragma unroll
        for (int b = 0; b < 4; b++)
            #pragma unroll
            for (int e = 0; e < 4; e++) acc[a][b][e] = 0.0f;

    const __nv_bfloat16* Ah[2] = { g_Lh  + ((size_t)gate << 20), nullptr };
    const __nv_bfloat16* Al[2] = { g_Ll  + ((size_t)gate << 20), nullptr };
    const __nv_bfloat16* Bh[2] = { g_XTh + ((size_t)(gate & 1) << 20), nullptr };
    const __nv_bfloat16* Bl[2] = { g_XTl + ((size_t)(gate & 1) << 20), nullptr };

    mainloop(sb, tid, 1, Ah, Al, Bh, Bl, rowTile, colTile, acc);

    // epilogue: split P into bf16 hi/lo
    const int lane = tid & 31, wid = tid >> 5;
    const int wm = wid >> 2, wn = wid & 3;
    __nv_bfloat16* dh = g_Ph + ((size_t)gate << 20);
    __nv_bfloat16* dl = g_Pl + ((size_t)gate << 20);
    const int m0 = rowTile + wm * 64 + (lane >> 2);
    const int n0 = colTile + wn * 32 + (lane & 3) * 2;
    #pragma unroll
    for (int mt = 0; mt < 4; mt++)
        #pragma unroll
        for (int h2 = 0; h2 < 2; h2++) {
            const int m = m0 + mt * 16 + h2 * 8;
            const size_t rowb = (size_t)m * NSZ;
            #pragma unroll
            for (int nt = 0; nt < 4; nt++) {
                float v0 = acc[mt][nt][h2 * 2 + 0];
                float v1 = acc[mt][nt][h2 * 2 + 1];
                __nv_bfloat16 h0 = __float2bfloat16_rn(v0);
                __nv_bfloat16 h1 = __float2bfloat16_rn(v1);
                __nv_bfloat16 l0 = __float2bfloat16_rn(v0 - __bfloat162float(h0));
                __nv_bfloat16 l1 = __float2bfloat16_rn(v1 - __bfloat162float(h1));
                __nv_bfloat162 hp = __halves2bfloat162(h0, h1);
                __nv_bfloat162 lp = __halves2bfloat162(l0, l1);
                *(uint32_t*)(dh + rowb + n0 + nt * 8) = *(uint32_t*)&hp;
                *(uint32_t*)(dl + rowb + n0 + nt * 8) = *(uint32_t*)&lp;
            }
        }
}

// ---------------- Kernel: phase 2  gates = act(P@R pair + biases) ----------
struct B8 { const float* b[8]; };

__global__ void __launch_bounds__(256, 1)
gemm2(B8 pb)
{
    extern __shared__ char smem[];
    const uint32_t sb = smem_u32(smem);
    const int tid = threadIdx.x;
    const int pr = blockIdx.z;                 // 0:i 1:f 2:g 3:o
    const int g0 = 2 * pr;
    const int rowTile = blockIdx.y * 128, colTile = blockIdx.x * 128;

    float acc[4][4][4];
    #pragma unroll
    for (int a = 0; a < 4; a++)
        #pragma unroll
        for (int b = 0; b < 4; b++)
            #pragma unroll
            for (int e = 0; e < 4; e++) acc[a][b][e] = 0.0f;

    const __nv_bfloat16* Ah[2] = { g_Ph  + ((size_t)g0 << 20), g_Ph  + ((size_t)(g0 + 1) << 20) };
    const __nv_bfloat16* Al[2] = { g_Pl  + ((size_t)g0 << 20), g_Pl  + ((size_t)(g0 + 1) << 20) };
    const __nv_bfloat16* Bh[2] = { g_RTh + ((size_t)g0 << 20), g_RTh + ((size_t)(g0 + 1) << 20) };
    const __nv_bfloat16* Bl[2] = { g_RTl + ((size_t)g0 << 20), g_RTl + ((size_t)(g0 + 1) << 20) };

    mainloop(sb, tid, 2, Ah, Al, Bh, Bl, rowTile, colTile, acc);

    // epilogue: + b0 + b1, activation, store fp32 gate
    const int lane = tid & 31, wid = tid >> 5;
    const int wm = wid >> 2, wn = wid & 3;
    const float* __restrict__ b0 = pb.b[g0];
    const float* __restrict__ b1 = pb.b[g0 + 1];
    float* dst = g_G + ((size_t)pr << 20);
    const bool is_tanh = (pr == 2);
    const int m0 = rowTile + wm * 64 + (lane >> 2);
    const int n0 = colTile + wn * 32 + (lane & 3) * 2;
    #pragma unroll
    for (int mt = 0; mt < 4; mt++)
        #pragma unroll
        for (int h2 = 0; h2 < 2; h2++) {
            const int m = m0 + mt * 16 + h2 * 8;
            const size_t rowb = (size_t)m * NSZ;
            #pragma unroll
            for (int nt = 0; nt < 4; nt++) {
                const size_t idx = rowb + n0 + nt * 8;
                float2 v0 = *(const float2*)(b0 + idx);
                float2 v1 = *(const float2*)(b1 + idx);
                float s0 = acc[mt][nt][h2 * 2 + 0] + v0.x + v1.x;
                float s1 = acc[mt][nt][h2 * 2 + 1] + v0.y + v1.y;
                float2 o;
                if (is_tanh) {
                    o.x = tanhf(s0); o.y = tanhf(s1);
                } else {
                    o.x = 1.0f / (1.0f + __expf(-s0));
                    o.y = 1.0f / (1.0f + __expf(-s1));
                }
                *(float2*)(dst + idx) = o;
            }
        }
}

// ---------------- Conversion kernels ----------------------------------------
__global__ void __launch_bounds__(256)
convL(B8 p)
{
    const int g = blockIdx.z;
    const size_t i = (size_t)blockIdx.x * 256 + threadIdx.x;   // float4 index
    float4 v = ((const float4*)p.b[g])[i];
    __nv_bfloat162 h01 = __floats2bfloat162_rn(v.x, v.y);
    __nv_bfloat162 h23 = __floats2bfloat162_rn(v.z, v.w);
    float4 lo;
    lo.x = v.x - __bfloat162float(__low2bfloat16(h01));
    lo.y = v.y - __bfloat162float(__high2bfloat16(h01));
    lo.z = v.z - __bfloat162float(__low2bfloat16(h23));
    lo.w = v.w - __bfloat162float(__high2bfloat16(h23));
    __nv_bfloat162 l01 = __floats2bfloat162_rn(lo.x, lo.y);
    __nv_bfloat162 l23 = __floats2bfloat162_rn(lo.z, lo.w);
    uint2 hv = make_uint2(*(uint32_t*)&h01, *(uint32_t*)&h23);
    uint2 lv = make_uint2(*(uint32_t*)&l01, *(uint32_t*)&l23);
    ((uint2*)(g_Lh + ((size_t)g << 20)))[i] = hv;
    ((uint2*)(g_Ll + ((size_t)g << 20)))[i] = lv;
}

struct P10 { const float* p[10]; };

__global__ void __launch_bounds__(256)
convT(P10 pp)
{
    __shared__ float t[32][33];
    const int z = blockIdx.z;
    const float* __restrict__ src = pp.p[z];
    __nv_bfloat16 *dh, *dl;
    if (z < 2) { dh = g_XTh + ((size_t)z << 20);       dl = g_XTl + ((size_t)z << 20); }
    else       { dh = g_RTh + ((size_t)(z - 2) << 20); dl = g_RTl + ((size_t)(z - 2) << 20); }

    const int tx = threadIdx.x & 31, ty = threadIdx.x >> 5;
    const int bx = blockIdx.x * 32, by = blockIdx.y * 32;
    #pragma unroll
    for (int j = 0; j < 4; j++)
        t[ty + j * 8][tx] = src[(size_t)(by + ty + j * 8) * NSZ + bx + tx];
    __syncthreads();
    #pragma unroll
    for (int j = 0; j < 4; j++) {
        float v = t[tx][ty + j * 8];
        __nv_bfloat16 h = __float2bfloat16_rn(v);
        __nv_bfloat16 l = __float2bfloat16_rn(v - __bfloat162float(h));
        const size_t o = (size_t)(bx + ty + j * 8) * NSZ + by + tx;
        dh[o] = h;
        dl[o] = l;
    }
}

// ---------------- Elementwise cell -------------------------------------------
__global__ void __launch_bounds__(256)
cellC(const float* __restrict__ c, float* __restrict__ out)
{
    const int idx = blockIdx.x * 256 + threadIdx.x;
    const float4* Gi = (const float4*)g_G;
    const float4* Gf = (const float4*)(g_G + (1ul << 20));
    const float4* Gg = (const float4*)(g_G + (2ul << 20));
    const float4* Go = (const float4*)(g_G + (3ul << 20));
    float4 vi = Gi[idx], vf = Gf[idx], vg = Gg[idx], vo = Go[idx];
    float4 vc = ((const float4*)c)[idx];
    float4 cn, hn;
    cn.x = vf.x * vc.x + vi.x * vg.x;
    cn.y = vf.y * vc.y + vi.y * vg.y;
    cn.z = vf.z * vc.z + vi.z * vg.z;
    cn.w = vf.w * vc.w + vi.w * vg.w;
    hn.x = vo.x * tanhf(cn.x);
    hn.y = vo.y * tanhf(cn.y);
    hn.z = vo.z * tanhf(cn.z);
    hn.w = vo.w * tanhf(cn.w);
    ((float4*)out)[idx] = hn;
    ((float4*)(out + (1ul << 20)))[idx] = cn;
}

// ---------------- launch -----------------------------------------------------
extern "C" void kernel_launch(void* const* d_in, const int* in_sizes, int n_in,
                              void* d_out, int out_size)
{
    (void)in_sizes; (void)n_in; (void)out_size;
    const float* x = (const float*)d_in[0];
    const float* h = (const float*)d_in[1];
    const float* c = (const float*)d_in[2];

    B8 pL, pB;
    P10 pT;
    pT.p[0] = x;
    pT.p[1] = h;
    for (int g = 0; g < 8; g++) {
        pL.b[g]     = (const float*)d_in[3 + 3 * g];   // L_g
        pT.p[2 + g] = (const float*)d_in[4 + 3 * g];   // R_g (transposed)
        pB.b[g]     = (const float*)d_in[5 + 3 * g];   // b_g
    }

    cudaFuncSetAttribute(gemm1, cudaFuncAttributeMaxDynamicSharedMemorySize, SMEM_TOTAL);
    cudaFuncSetAttribute(gemm2, cudaFuncAttributeMaxDynamicSharedMemorySize, SMEM_TOTAL);

    convL<<<dim3(1024, 1, 8), 256>>>(pL);
    convT<<<dim3(32, 32, 10), 256>>>(pT);
    gemm1<<<dim3(8, 8, 8), 256, SMEM_TOTAL>>>();
    gemm2<<<dim3(8, 8, 4), 256, SMEM_TOTAL>>>(pB);
    cellC<<<dim3(1024), 256>>>(c, (float*)d_out);
}

// round 5
// speedup vs baseline: 2.5681x; 1.1828x over previous
#include <cuda_runtime.h>
#include <cuda_bf16.h>
#include <cstdint>
#include <math.h>

#define NSZ 1024

// ---------------- scratch (static device globals; no runtime alloc) --------
__device__ __align__(16) __nv_bfloat16 g_Lh[8u << 20];
__device__ __align__(16) __nv_bfloat16 g_Ll[8u << 20];
__device__ __align__(16) __nv_bfloat16 g_XTh[2u << 20];
__device__ __align__(16) __nv_bfloat16 g_XTl[2u << 20];
__device__ __align__(16) __nv_bfloat16 g_RTh[8u << 20];
__device__ __align__(16) __nv_bfloat16 g_RTl[8u << 20];
__device__ __align__(16) __nv_bfloat16 g_Ph[8u << 20];
__device__ __align__(16) __nv_bfloat16 g_Pl[8u << 20];
__device__ __align__(16) float g_G[4u << 20];

// ---------------- SMEM stage layout ----------------------------------------
#define OFF_AL 8192
#define OFF_BH 16384
#define OFF_BL 24576
#define STAGE_BYTES 32768
#define NSTAGES 3
#define SMEM_TOTAL (NSTAGES * STAGE_BYTES)   // 96 KB -> 2 CTAs/SM

// ---------------- PTX helpers (all baseline sm_80-level) --------------------
__device__ __forceinline__ uint32_t smem_u32(const void* p) {
    uint32_t a;
    asm("{ .reg .u64 t; cvta.to.shared.u64 t, %1; cvt.u32.u64 %0, t; }"
        : "=r"(a) : "l"(p));
    return a;
}
__device__ __forceinline__ void cp16(uint32_t smem, const void* g) {
    asm volatile("cp.async.cg.shared.global [%0], [%1], 16;"
                 :: "r"(smem), "l"(g));
}
__device__ __forceinline__ void cp_commit() {
    asm volatile("cp.async.commit_group;" ::: "memory");
}
__device__ __forceinline__ void cp_wait1() {
    asm volatile("cp.async.wait_group 1;" ::: "memory");
}
__device__ __forceinline__ void ldsm_x4(uint32_t (&r)[4], uint32_t addr) {
    asm volatile("ldmatrix.sync.aligned.m8n8.x4.shared.b16 {%0,%1,%2,%3}, [%4];"
                 : "=r"(r[0]), "=r"(r[1]), "=r"(r[2]), "=r"(r[3]) : "r"(addr));
}
__device__ __forceinline__ void mma16816(float (&d)[4], const uint32_t (&a)[4],
                                         uint32_t b0, uint32_t b1) {
    asm volatile("mma.sync.aligned.m16n8k16.row.col.f32.bf16.bf16.f32 "
                 "{%0,%1,%2,%3}, {%4,%5,%6,%7}, {%8,%9}, {%0,%1,%2,%3};"
                 : "+f"(d[0]), "+f"(d[1]), "+f"(d[2]), "+f"(d[3])
                 : "r"(a[0]), "r"(a[1]), "r"(a[2]), "r"(a[3]), "r"(b0), "r"(b1));
}

// swizzle: 16B chunk j within 64B row r -> j ^ ((r>>1)&3)
__device__ __forceinline__ uint32_t sw_off(int r, int j) {
    return (uint32_t)(r * 64 + ((j ^ ((r >> 1) & 3)) << 4));
}

// load one [128 rows x 32 k] bf16 tile into swizzled SMEM via cp.async
__device__ __forceinline__ void issue_mat(const __nv_bfloat16* __restrict__ src,
                                          int row0, int k0, uint32_t dst, int tid) {
    #pragma unroll
    for (int i = 0; i < 2; i++) {
        int f = tid + i * 256;
        int r = f >> 2;
        int j = f & 3;
        cp16(dst + sw_off(r, j), src + (size_t)(row0 + r) * NSZ + k0 + j * 8);
    }
}

__device__ __forceinline__ void issue_stage(uint32_t sb, int buf,
    const __nv_bfloat16* Ah, const __nv_bfloat16* Al,
    const __nv_bfloat16* Bh, const __nv_bfloat16* Bl,
    int rowTile, int colTile, int k0, int tid)
{
    uint32_t base = sb + buf * STAGE_BYTES;
    issue_mat(Ah, rowTile, k0, base,          tid);
    issue_mat(Al, rowTile, k0, base + OFF_AL, tid);
    issue_mat(Bh, colTile, k0, base + OFF_BH, tid);
    issue_mat(Bl, colTile, k0, base + OFF_BL, tid);
    cp_commit();
}

// ---------------- split-bf16 GEMM mainloop ----------------------------------
// acc += Ah*Bh + Ah*Bl + Al*Bh   (K = 1024 per half, nhalf halves)
__device__ __forceinline__ void mainloop(
    uint32_t sb, int tid, int nhalf,
    const __nv_bfloat16* const* Ah, const __nv_bfloat16* const* Al,
    const __nv_bfloat16* const* Bh, const __nv_bfloat16* const* Bl,
    int rowTile, int colTile, float (&acc)[4][4][4])
{
    const int lane = tid & 31;
    const int wid  = tid >> 5;
    const int wm   = wid >> 2;       // 0..1  (64 rows)
    const int wn   = wid & 3;        // 0..3  (32 cols)

    // precompute ldmatrix lane offsets (relative to stage base)
    uint32_t aOff[2][4], bOff[2][2];
    #pragma unroll
    for (int ks = 0; ks < 2; ks++) {
        #pragma unroll
        for (int mt = 0; mt < 4; mt++) {
            int r = wm * 64 + mt * 16 + (lane & 15);
            int j = ks * 2 + (lane >> 4);
            aOff[ks][mt] = sw_off(r, j);
        }
        #pragma unroll
        for (int bp = 0; bp < 2; bp++) {
            int r = wn * 32 + bp * 16 + ((lane >> 4) * 8) + (lane & 7);
            int j = ks * 2 + ((lane >> 3) & 1);
            bOff[ks][bp] = OFF_BH + sw_off(r, j);
        }
    }

    const int NS = 32 * nhalf;

    // prologue: 2 stages in flight (buffers 0,1)
    issue_stage(sb, 0, Ah[0], Al[0], Bh[0], Bl[0], rowTile, colTile, 0,  tid);
    issue_stage(sb, 1, Ah[0], Al[0], Bh[0], Bl[0], rowTile, colTile, 32, tid);

    int cbuf = 0;   // buffer holding stage s
    int ibuf = 2;   // buffer to fill with stage s+2
    #pragma unroll 1
    for (int s = 0; s < NS; s++) {
        cp_wait1();            // oldest in-flight group (stage s) complete
        __syncthreads();       // all warps done consuming stage s-1 (buf ibuf)
        int sn = s + 2;
        if (sn < NS) {
            int hf = sn >> 5;
            issue_stage(sb, ibuf, Ah[hf], Al[hf], Bh[hf], Bl[hf],
                        rowTile, colTile, (sn & 31) * 32, tid);
        } else {
            cp_commit();   // keep group numbering aligned
        }

        uint32_t base = sb + cbuf * STAGE_BYTES;
        cbuf = (cbuf == 2) ? 0 : cbuf + 1;
        ibuf = (ibuf == 2) ? 0 : ibuf + 1;

        #pragma unroll
        for (int ks = 0; ks < 2; ks++) {
            uint32_t Af[4][4], Lf[4][4], Bf[2][4];
            #pragma unroll
            for (int mt = 0; mt < 4; mt++) ldsm_x4(Af[mt], base + aOff[ks][mt]);
            #pragma unroll
            for (int mt = 0; mt < 4; mt++) ldsm_x4(Lf[mt], base + OFF_AL + aOff[ks][mt]);
            #pragma unroll
            for (int bp = 0; bp < 2; bp++) ldsm_x4(Bf[bp], base + bOff[ks][bp]);

            // pass hh
            #pragma unroll
            for (int mt = 0; mt < 4; mt++)
                #pragma unroll
                for (int nt = 0; nt < 4; nt++)
                    mma16816(acc[mt][nt], Af[mt],
                             Bf[nt >> 1][(nt & 1) * 2], Bf[nt >> 1][(nt & 1) * 2 + 1]);
            // pass lh (A-lo x B-hi)
            #pragma unroll
            for (int mt = 0; mt < 4; mt++)
                #pragma unroll
                for (int nt = 0; nt < 4; nt++)
                    mma16816(acc[mt][nt], Lf[mt],
                             Bf[nt >> 1][(nt & 1) * 2], Bf[nt >> 1][(nt & 1) * 2 + 1]);
            // load B-lo, pass hl (A-hi x B-lo)
            #pragma unroll
            for (int bp = 0; bp < 2; bp++) ldsm_x4(Bf[bp], base + 8192 + bOff[ks][bp]);
            #pragma unroll
            for (int mt = 0; mt < 4; mt++)
                #pragma unroll
                for (int nt = 0; nt < 4; nt++)
                    mma16816(acc[mt][nt], Af[mt],
                             Bf[nt >> 1][(nt & 1) * 2], Bf[nt >> 1][(nt & 1) * 2 + 1]);
        }
    }
}

// ---------------- Kernel: phase 1  P_g = L_g @ X_g --------------------------
__global__ void __launch_bounds__(256, 2)
gemm1()
{
    extern __shared__ char smem[];
    const uint32_t sb = smem_u32(smem);
    const int tid = threadIdx.x;
    const int gate = blockIdx.z;
    const int rowTile = blockIdx.y * 128, colTile = blockIdx.x * 128;

    float acc[4][4][4];
    #pragma unroll
    for (int a = 0; a < 4; a++)
        #pragma unroll
        for (int b = 0; b < 4; b++)
            #pragma unroll
            for (int e = 0; e < 4; e++) acc[a][b][e] = 0.0f;

    const __nv_bfloat16* Ah[2] = { g_Lh  + ((size_t)gate << 20), nullptr };
    const __nv_bfloat16* Al[2] = { g_Ll  + ((size_t)gate << 20), nullptr };
    const __nv_bfloat16* Bh[2] = { g_XTh + ((size_t)(gate & 1) << 20), nullptr };
    const __nv_bfloat16* Bl[2] = { g_XTl + ((size_t)(gate & 1) << 20), nullptr };

    mainloop(sb, tid, 1, Ah, Al, Bh, Bl, rowTile, colTile, acc);

    // epilogue: split P into bf16 hi/lo
    const int lane = tid & 31, wid = tid >> 5;
    const int wm = wid >> 2, wn = wid & 3;
    __nv_bfloat16* dh = g_Ph + ((size_t)gate << 20);
    __nv_bfloat16* dl = g_Pl + ((size_t)gate << 20);
    const int m0 = rowTile + wm * 64 + (lane >> 2);
    const int n0 = colTile + wn * 32 + (lane & 3) * 2;
    #pragma unroll
    for (int mt = 0; mt < 4; mt++)
        #pragma unroll
        for (int h2 = 0; h2 < 2; h2++) {
            const int m = m0 + mt * 16 + h2 * 8;
            const size_t rowb = (size_t)m * NSZ;
            #pragma unroll
            for (int nt = 0; nt < 4; nt++) {
                float v0 = acc[mt][nt][h2 * 2 + 0];
                float v1 = acc[mt][nt][h2 * 2 + 1];
                __nv_bfloat16 h0 = __float2bfloat16_rn(v0);
                __nv_bfloat16 h1 = __float2bfloat16_rn(v1);
                __nv_bfloat16 l0 = __float2bfloat16_rn(v0 - __bfloat162float(h0));
                __nv_bfloat16 l1 = __float2bfloat16_rn(v1 - __bfloat162float(h1));
                __nv_bfloat162 hp = __halves2bfloat162(h0, h1);
                __nv_bfloat162 lp = __halves2bfloat162(l0, l1);
                *(uint32_t*)(dh + rowb + n0 + nt * 8) = *(uint32_t*)&hp;
                *(uint32_t*)(dl + rowb + n0 + nt * 8) = *(uint32_t*)&lp;
            }
        }
}

// ---------------- Kernel: phase 2  gates = act(P@R pair + biases) ----------
struct B8 { const float* b[8]; };

__global__ void __launch_bounds__(256, 2)
gemm2(B8 pb)
{
    extern __shared__ char smem[];
    const uint32_t sb = smem_u32(smem);
    const int tid = threadIdx.x;
    const int pr = blockIdx.z;                 // 0:i 1:f 2:g 3:o
    const int g0 = 2 * pr;
    const int rowTile = blockIdx.y * 128, colTile = blockIdx.x * 128;

    float acc[4][4][4];
    #pragma unroll
    for (int a = 0; a < 4; a++)
        #pragma unroll
        for (int b = 0; b < 4; b++)
            #pragma unroll
            for (int e = 0; e < 4; e++) acc[a][b][e] = 0.0f;

    const __nv_bfloat16* Ah[2] = { g_Ph  + ((size_t)g0 << 20), g_Ph  + ((size_t)(g0 + 1) << 20) };
    const __nv_bfloat16* Al[2] = { g_Pl  + ((size_t)g0 << 20), g_Pl  + ((size_t)(g0 + 1) << 20) };
    const __nv_bfloat16* Bh[2] = { g_RTh + ((size_t)g0 << 20), g_RTh + ((size_t)(g0 + 1) << 20) };
    const __nv_bfloat16* Bl[2] = { g_RTl + ((size_t)g0 << 20), g_RTl + ((size_t)(g0 + 1) << 20) };

    mainloop(sb, tid, 2, Ah, Al, Bh, Bl, rowTile, colTile, acc);

    // epilogue: + b0 + b1, activation, store fp32 gate
    const int lane = tid & 31, wid = tid >> 5;
    const int wm = wid >> 2, wn = wid & 3;
    const float* __restrict__ b0 = pb.b[g0];
    const float* __restrict__ b1 = pb.b[g0 + 1];
    float* dst = g_G + ((size_t)pr << 20);
    const bool is_tanh = (pr == 2);
    const int m0 = rowTile + wm * 64 + (lane >> 2);
    const int n0 = colTile + wn * 32 + (lane & 3) * 2;
    #pragma unroll
    for (int mt = 0; mt < 4; mt++)
        #pragma unroll
        for (int h2 = 0; h2 < 2; h2++) {
            const int m = m0 + mt * 16 + h2 * 8;
            const size_t rowb = (size_t)m * NSZ;
            #pragma unroll
            for (int nt = 0; nt < 4; nt++) {
                const size_t idx = rowb + n0 + nt * 8;
                float2 v0 = *(const float2*)(b0 + idx);
                float2 v1 = *(const float2*)(b1 + idx);
                float s0 = acc[mt][nt][h2 * 2 + 0] + v0.x + v1.x;
                float s1 = acc[mt][nt][h2 * 2 + 1] + v0.y + v1.y;
                float2 o;
                if (is_tanh) {
                    o.x = tanhf(s0); o.y = tanhf(s1);
                } else {
                    o.x = 1.0f / (1.0f + __expf(-s0));
                    o.y = 1.0f / (1.0f + __expf(-s1));
                }
                *(float2*)(dst + idx) = o;
            }
        }
}

// ---------------- Conversion kernels ----------------------------------------
__global__ void __launch_bounds__(256)
convL(B8 p)
{
    const int g = blockIdx.z;
    const size_t i = (size_t)blockIdx.x * 256 + threadIdx.x;   // float4 index
    float4 v = ((const float4*)p.b[g])[i];
    __nv_bfloat162 h01 = __floats2bfloat162_rn(v.x, v.y);
    __nv_bfloat162 h23 = __floats2bfloat162_rn(v.z, v.w);
    float4 lo;
    lo.x = v.x - __bfloat162float(__low2bfloat16(h01));
    lo.y = v.y - __bfloat162float(__high2bfloat16(h01));
    lo.z = v.z - __bfloat162float(__low2bfloat16(h23));
    lo.w = v.w - __bfloat162float(__high2bfloat16(h23));
    __nv_bfloat162 l01 = __floats2bfloat162_rn(lo.x, lo.y);
    __nv_bfloat162 l23 = __floats2bfloat162_rn(lo.z, lo.w);
    uint2 hv = make_uint2(*(uint32_t*)&h01, *(uint32_t*)&h23);
    uint2 lv = make_uint2(*(uint32_t*)&l01, *(uint32_t*)&l23);
    ((uint2*)(g_Lh + ((size_t)g << 20)))[i] = hv;
    ((uint2*)(g_Ll + ((size_t)g << 20)))[i] = lv;
}

struct P10 { const float* p[10]; };

__global__ void __launch_bounds__(256)
convT(P10 pp)
{
    __shared__ float t[32][33];
    const int z = blockIdx.z;
    const float* __restrict__ src = pp.p[z];
    __nv_bfloat16 *dh, *dl;
    if (z < 2) { dh = g_XTh + ((size_t)z << 20);       dl = g_XTl + ((size_t)z << 20); }
    else       { dh = g_RTh + ((size_t)(z - 2) << 20); dl = g_RTl + ((size_t)(z - 2) << 20); }

    const int tx = threadIdx.x & 31, ty = threadIdx.x >> 5;
    const int bx = blockIdx.x * 32, by = blockIdx.y * 32;
    #pragma unroll
    for (int j = 0; j < 4; j++)
        t[ty + j * 8][tx] = src[(size_t)(by + ty + j * 8) * NSZ + bx + tx];
    __syncthreads();
    #pragma unroll
    for (int j = 0; j < 4; j++) {
        float v = t[tx][ty + j * 8];
        __nv_bfloat16 h = __float2bfloat16_rn(v);
        __nv_bfloat16 l = __float2bfloat16_rn(v - __bfloat162float(h));
        const size_t o = (size_t)(bx + ty + j * 8) * NSZ + by + tx;
        dh[o] = h;
        dl[o] = l;
    }
}

// ---------------- Elementwise cell -------------------------------------------
__global__ void __launch_bounds__(256)
cellC(const float* __restrict__ c, float* __restrict__ out)
{
    const int idx = blockIdx.x * 256 + threadIdx.x;
    const float4* Gi = (const float4*)g_G;
    const float4* Gf = (const float4*)(g_G + (1ul << 20));
    const float4* Gg = (const float4*)(g_G + (2ul << 20));
    const float4* Go = (const float4*)(g_G + (3ul << 20));
    float4 vi = Gi[idx], vf = Gf[idx], vg = Gg[idx], vo = Go[idx];
    float4 vc = ((const float4*)c)[idx];
    float4 cn, hn;
    cn.x = vf.x * vc.x + vi.x * vg.x;
    cn.y = vf.y * vc.y + vi.y * vg.y;
    cn.z = vf.z * vc.z + vi.z * vg.z;
    cn.w = vf.w * vc.w + vi.w * vg.w;
    hn.x = vo.x * tanhf(cn.x);
    hn.y = vo.y * tanhf(cn.y);
    hn.z = vo.z * tanhf(cn.z);
    hn.w = vo.w * tanhf(cn.w);
    ((float4*)out)[idx] = hn;
    ((float4*)(out + (1ul << 20)))[idx] = cn;
}

// ---------------- launch -----------------------------------------------------
extern "C" void kernel_launch(void* const* d_in, const int* in_sizes, int n_in,
                              void* d_out, int out_size)
{
    (void)in_sizes; (void)n_in; (void)out_size;
    const float* x = (const float*)d_in[0];
    const float* h = (const float*)d_in[1];
    const float* c = (const float*)d_in[2];

    B8 pL, pB;
    P10 pT;
    pT.p[0] = x;
    pT.p[1] = h;
    for (int g = 0; g < 8; g++) {
        pL.b[g]     = (const float*)d_in[3 + 3 * g];   // L_g
        pT.p[2 + g] = (const float*)d_in[4 + 3 * g];   // R_g (transposed)
        pB.b[g]     = (const float*)d_in[5 + 3 * g];   // b_g
    }

    cudaFuncSetAttribute(gemm1, cudaFuncAttributeMaxDynamicSharedMemorySize, SMEM_TOTAL);
    cudaFuncSetAttribute(gemm2, cudaFuncAttributeMaxDynamicSharedMemorySize, SMEM_TOTAL);

    convL<<<dim3(1024, 1, 8), 256>>>(pL);
    convT<<<dim3(32, 32, 10), 256>>>(pT);
    gemm1<<<dim3(8, 8, 8), 256, SMEM_TOTAL>>>();
    gemm2<<<dim3(8, 8, 4), 256, SMEM_TOTAL>>>(pB);
    cellC<<<dim3(1024), 256>>>(c, (float*)d_out);
}

// round 7
// speedup vs baseline: 2.6403x; 1.0282x over previous
#include <cuda_runtime.h>
#include <cuda_bf16.h>
#include <cstdint>
#include <math.h>

#define NSZ 1024

// ---------------- scratch (static device globals; no runtime alloc) --------
__device__ __align__(16) __nv_bfloat16 g_Lh[8u << 20];
__device__ __align__(16) __nv_bfloat16 g_Ll[8u << 20];
__device__ __align__(16) __nv_bfloat16 g_XTh[2u << 20];
__device__ __align__(16) __nv_bfloat16 g_XTl[2u << 20];
__device__ __align__(16) __nv_bfloat16 g_RTh[8u << 20];
__device__ __align__(16) __nv_bfloat16 g_RTl[8u << 20];
__device__ __align__(16) __nv_bfloat16 g_Ph[8u << 20];
__device__ __align__(16) __nv_bfloat16 g_Pl[8u << 20];
__device__ __align__(16) float g_G[4u << 20];

// ---------------- SMEM stage layout ----------------------------------------
#define OFF_AL 8192
#define OFF_BH 16384
#define OFF_BL 24576
#define STAGE_BYTES 32768
#define NSTAGES 3
#define MBAR_OFF (NSTAGES * STAGE_BYTES)          // 98304
#define SMEM_TOTAL (MBAR_OFF + 64)                // + mbarriers

// ---------------- PTX helpers (all baseline sm_80/90-level) -----------------
__device__ __forceinline__ uint32_t smem_u32(const void* p) {
    uint32_t a;
    asm("{ .reg .u64 t; cvta.to.shared.u64 t, %1; cvt.u32.u64 %0, t; }"
        : "=r"(a) : "l"(p));
    return a;
}
__device__ __forceinline__ void cp16(uint32_t smem, const void* g) {
    asm volatile("cp.async.cg.shared.global [%0], [%1], 16;"
                 :: "r"(smem), "l"(g));
}
__device__ __forceinline__ void mbar_init(uint32_t a, uint32_t cnt) {
    asm volatile("mbarrier.init.shared.b64 [%0], %1;" :: "r"(a), "r"(cnt) : "memory");
}
__device__ __forceinline__ void mbar_arrive(uint32_t a) {
    asm volatile("mbarrier.arrive.shared.b64 _, [%0];" :: "r"(a) : "memory");
}
// .noinc: does NOT bump the pending count; performs one async arrive when all
// of this thread's prior cp.asyncs complete. Init count must equal #threads.
__device__ __forceinline__ void cp_mbar_arrive(uint32_t a) {
    asm volatile("cp.async.mbarrier.arrive.noinc.shared.b64 [%0];" :: "r"(a) : "memory");
}
__device__ __forceinline__ void mbar_wait(uint32_t a, uint32_t phase) {
    asm volatile("{\n\t.reg .pred P;\n\tWL%=:\n\t"
                 "mbarrier.try_wait.parity.acquire.cta.shared::cta.b64 P, [%0], %1, 0x989680;\n\t"
                 "@!P bra WL%=;\n\t}" :: "r"(a), "r"(phase) : "memory");
}
__device__ __forceinline__ void ldsm_x4(uint32_t (&r)[4], uint32_t addr) {
    asm volatile("ldmatrix.sync.aligned.m8n8.x4.shared.b16 {%0,%1,%2,%3}, [%4];"
                 : "=r"(r[0]), "=r"(r[1]), "=r"(r[2]), "=r"(r[3]) : "r"(addr));
}
__device__ __forceinline__ void mma16816(float (&d)[4], const uint32_t (&a)[4],
                                         uint32_t b0, uint32_t b1) {
    asm volatile("mma.sync.aligned.m16n8k16.row.col.f32.bf16.bf16.f32 "
                 "{%0,%1,%2,%3}, {%4,%5,%6,%7}, {%8,%9}, {%0,%1,%2,%3};"
                 : "+f"(d[0]), "+f"(d[1]), "+f"(d[2]), "+f"(d[3])
                 : "r"(a[0]), "r"(a[1]), "r"(a[2]), "r"(a[3]), "r"(b0), "r"(b1));
}

// swizzle: 16B chunk j within 64B row r -> j ^ ((r>>1)&3)
__device__ __forceinline__ uint32_t sw_off(int r, int j) {
    return (uint32_t)(r * 64 + ((j ^ ((r >> 1) & 3)) << 4));
}

// load one [128 rows x 32 k] bf16 tile into swizzled SMEM via cp.async
__device__ __forceinline__ void issue_mat(const __nv_bfloat16* __restrict__ src,
                                          int row0, int k0, uint32_t dst, int tid) {
    #pragma unroll
    for (int i = 0; i < 2; i++) {
        int f = tid + i * 256;
        int r = f >> 2;
        int j = f & 3;
        cp16(dst + sw_off(r, j), src + (size_t)(row0 + r) * NSZ + k0 + j * 8);
    }
}

__device__ __forceinline__ void issue_stage(uint32_t sb, int buf,
    const __nv_bfloat16* Ah, const __nv_bfloat16* Al,
    const __nv_bfloat16* Bh, const __nv_bfloat16* Bl,
    int rowTile, int colTile, int k0, int tid)
{
    uint32_t base = sb + buf * STAGE_BYTES;
    issue_mat(Ah, rowTile, k0, base,          tid);
    issue_mat(Al, rowTile, k0, base + OFF_AL, tid);
    issue_mat(Bh, colTile, k0, base + OFF_BH, tid);
    issue_mat(Bl, colTile, k0, base + OFF_BL, tid);
}

// ---------------- split-bf16 GEMM mainloop (mbarrier ring, depth 3) ---------
// acc += Ah*Bh + Ah*Bl + Al*Bh   (K = 1024 per half, nhalf halves)
__device__ __forceinline__ void mainloop(
    uint32_t sb, int tid, int nhalf,
    const __nv_bfloat16* const* Ah, const __nv_bfloat16* const* Al,
    const __nv_bfloat16* const* Bh, const __nv_bfloat16* const* Bl,
    int rowTile, int colTile, float (&acc)[4][4][4])
{
    const int lane = tid & 31;
    const int wid  = tid >> 5;
    const int wm   = wid >> 2;       // 0..1  (64 rows)
    const int wn   = wid & 3;        // 0..3  (32 cols)

    const uint32_t fullB  = sb + MBAR_OFF;        // full[b]  = +b*8
    const uint32_t emptyB = sb + MBAR_OFF + 24;   // empty[b] = +b*8

    if (tid == 0) {
        #pragma unroll
        for (int b = 0; b < 3; b++) {
            mbar_init(fullB  + b * 8, 256);
            mbar_init(emptyB + b * 8, 256);
        }
    }
    __syncthreads();   // inits visible before any arrive

    // precompute ldmatrix lane offsets (relative to stage base)
    uint32_t aOff[2][4], bOff[2][2];
    #pragma unroll
    for (int ks = 0; ks < 2; ks++) {
        #pragma unroll
        for (int mt = 0; mt < 4; mt++) {
            int r = wm * 64 + mt * 16 + (lane & 15);
            int j = ks * 2 + (lane >> 4);
            aOff[ks][mt] = sw_off(r, j);
        }
        #pragma unroll
        for (int bp = 0; bp < 2; bp++) {
            int r = wn * 32 + bp * 16 + ((lane >> 4) * 8) + (lane & 7);
            int j = ks * 2 + ((lane >> 3) & 1);
            bOff[ks][bp] = OFF_BH + sw_off(r, j);
        }
    }

    const int NS = 32 * nhalf;

    // prologue: fill all 3 buffers (stages 0,1,2 are in half 0)
    #pragma unroll
    for (int s = 0; s < 3; s++) {
        issue_stage(sb, s, Ah[0], Al[0], Bh[0], Bl[0],
                    rowTile, colTile, s * 32, tid);
        cp_mbar_arrive(fullB + s * 8);
    }

    uint32_t fmask = 0, emask = 0;
    int b = 0;
    #pragma unroll 1
    for (int s = 0; s < NS; s++) {
        // wait buffer full (acquire: makes peers' cp.async data visible)
        mbar_wait(fullB + b * 8, (fmask >> b) & 1);
        fmask ^= 1u << b;

        const uint32_t base = sb + b * STAGE_BYTES;
        #pragma unroll
        for (int ks = 0; ks < 2; ks++) {
            uint32_t Af[4][4], Lf[4][4], Bf[2][4];
            #pragma unroll
            for (int mt = 0; mt < 4; mt++) ldsm_x4(Af[mt], base + aOff[ks][mt]);
            #pragma unroll
            for (int mt = 0; mt < 4; mt++) ldsm_x4(Lf[mt], base + OFF_AL + aOff[ks][mt]);
            #pragma unroll
            for (int bp = 0; bp < 2; bp++) ldsm_x4(Bf[bp], base + bOff[ks][bp]);

            // pass hh
            #pragma unroll
            for (int mt = 0; mt < 4; mt++)
                #pragma unroll
                for (int nt = 0; nt < 4; nt++)
                    mma16816(acc[mt][nt], Af[mt],
                             Bf[nt >> 1][(nt & 1) * 2], Bf[nt >> 1][(nt & 1) * 2 + 1]);
            // pass lh (A-lo x B-hi)
            #pragma unroll
            for (int mt = 0; mt < 4; mt++)
                #pragma unroll
                for (int nt = 0; nt < 4; nt++)
                    mma16816(acc[mt][nt], Lf[mt],
                             Bf[nt >> 1][(nt & 1) * 2], Bf[nt >> 1][(nt & 1) * 2 + 1]);
            // load B-lo (last reads of this buffer for this ks)
            #pragma unroll
            for (int bp = 0; bp < 2; bp++) ldsm_x4(Bf[bp], base + 8192 + bOff[ks][bp]);
            if (ks == 1) mbar_arrive(emptyB + b * 8);   // all my reads of buf b done
            // pass hl (A-hi x B-lo)
            #pragma unroll
            for (int mt = 0; mt < 4; mt++)
                #pragma unroll
                for (int nt = 0; nt < 4; nt++)
                    mma16816(acc[mt][nt], Af[mt],
                             Bf[nt >> 1][(nt & 1) * 2], Bf[nt >> 1][(nt & 1) * 2 + 1]);
        }

        // refill this buffer for stage s+3 (after my MMAs; peers' LDSMs done by now)
        const int sn = s + 3;
        if (sn < NS) {
            mbar_wait(emptyB + b * 8, (emask >> b) & 1);
            emask ^= 1u << b;
            const int hf = sn >> 5;
            issue_stage(sb, b, Ah[hf], Al[hf], Bh[hf], Bl[hf],
                        rowTile, colTile, (sn & 31) * 32, tid);
            cp_mbar_arrive(fullB + b * 8);
        }
        b = (b == 2) ? 0 : b + 1;
    }
}

// ---------------- Kernel: phase 1  P_g = L_g @ X_g --------------------------
__global__ void __launch_bounds__(256, 2)
gemm1()
{
    extern __shared__ char smem[];
    const uint32_t sb = smem_u32(smem);
    const int tid = threadIdx.x;
    const int gate = blockIdx.z;
    const int rowTile = blockIdx.y * 128, colTile = blockIdx.x * 128;

    float acc[4][4][4];
    #pragma unroll
    for (int a = 0; a < 4; a++)
        #pragma unroll
        for (int b = 0; b < 4; b++)
            #pragma unroll
            for (int e = 0; e < 4; e++) acc[a][b][e] = 0.0f;

    const __nv_bfloat16* Ah[2] = { g_Lh  + ((size_t)gate << 20), nullptr };
    const __nv_bfloat16* Al[2] = { g_Ll  + ((size_t)gate << 20), nullptr };
    const __nv_bfloat16* Bh[2] = { g_XTh + ((size_t)(gate & 1) << 20), nullptr };
    const __nv_bfloat16* Bl[2] = { g_XTl + ((size_t)(gate & 1) << 20), nullptr };

    mainloop(sb, tid, 1, Ah, Al, Bh, Bl, rowTile, colTile, acc);

    // epilogue: split P into bf16 hi/lo
    const int lane = tid & 31, wid = tid >> 5;
    const int wm = wid >> 2, wn = wid & 3;
    __nv_bfloat16* dh = g_Ph + ((size_t)gate << 20);
    __nv_bfloat16* dl = g_Pl + ((size_t)gate << 20);
    const int m0 = rowTile + wm * 64 + (lane >> 2);
    const int n0 = colTile + wn * 32 + (lane & 3) * 2;
    #pragma unroll
    for (int mt = 0; mt < 4; mt++)
        #pragma unroll
        for (int h2 = 0; h2 < 2; h2++) {
            const int m = m0 + mt * 16 + h2 * 8;
            const size_t rowb = (size_t)m * NSZ;
            #pragma unroll
            for (int nt = 0; nt < 4; nt++) {
                float v0 = acc[mt][nt][h2 * 2 + 0];
                float v1 = acc[mt][nt][h2 * 2 + 1];
                __nv_bfloat16 h0 = __float2bfloat16_rn(v0);
                __nv_bfloat16 h1 = __float2bfloat16_rn(v1);
                __nv_bfloat16 l0 = __float2bfloat16_rn(v0 - __bfloat162float(h0));
                __nv_bfloat16 l1 = __float2bfloat16_rn(v1 - __bfloat162float(h1));
                __nv_bfloat162 hp = __halves2bfloat162(h0, h1);
                __nv_bfloat162 lp = __halves2bfloat162(l0, l1);
                *(uint32_t*)(dh + rowb + n0 + nt * 8) = *(uint32_t*)&hp;
                *(uint32_t*)(dl + rowb + n0 + nt * 8) = *(uint32_t*)&lp;
            }
        }
}

// ---------------- Kernel: phase 2  gates = act(P@R pair + biases) ----------
struct B8 { const float* b[8]; };

__global__ void __launch_bounds__(256, 2)
gemm2(B8 pb)
{
    extern __shared__ char smem[];
    const uint32_t sb = smem_u32(smem);
    const int tid = threadIdx.x;
    const int pr = blockIdx.z;                 // 0:i 1:f 2:g 3:o
    const int g0 = 2 * pr;
    const int rowTile = blockIdx.y * 128, colTile = blockIdx.x * 128;

    float acc[4][4][4];
    #pragma unroll
    for (int a = 0; a < 4; a++)
        #pragma unroll
        for (int b = 0; b < 4; b++)
            #pragma unroll
            for (int e = 0; e < 4; e++) acc[a][b][e] = 0.0f;

    const __nv_bfloat16* Ah[2] = { g_Ph  + ((size_t)g0 << 20), g_Ph  + ((size_t)(g0 + 1) << 20) };
    const __nv_bfloat16* Al[2] = { g_Pl  + ((size_t)g0 << 20), g_Pl  + ((size_t)(g0 + 1) << 20) };
    const __nv_bfloat16* Bh[2] = { g_RTh + ((size_t)g0 << 20), g_RTh + ((size_t)(g0 + 1) << 20) };
    const __nv_bfloat16* Bl[2] = { g_RTl + ((size_t)g0 << 20), g_RTl + ((size_t)(g0 + 1) << 20) };

    mainloop(sb, tid, 2, Ah, Al, Bh, Bl, rowTile, colTile, acc);

    // epilogue: + b0 + b1, activation, store fp32 gate
    const int lane = tid & 31, wid = tid >> 5;
    const int wm = wid >> 2, wn = wid & 3;
    const float* __restrict__ b0 = pb.b[g0];
    const float* __restrict__ b1 = pb.b[g0 + 1];
    float* dst = g_G + ((size_t)pr << 20);
    const bool is_tanh = (pr == 2);
    const int m0 = rowTile + wm * 64 + (lane >> 2);
    const int n0 = colTile + wn * 32 + (lane & 3) * 2;
    #pragma unroll
    for (int mt = 0; mt < 4; mt++)
        #pragma unroll
        for (int h2 = 0; h2 < 2; h2++) {
            const int m = m0 + mt * 16 + h2 * 8;
            const size_t rowb = (size_t)m * NSZ;
            #pragma unroll
            for (int nt = 0; nt < 4; nt++) {
                const size_t idx = rowb + n0 + nt * 8;
                float2 v0 = *(const float2*)(b0 + idx);
                float2 v1 = *(const float2*)(b1 + idx);
                float s0 = acc[mt][nt][h2 * 2 + 0] + v0.x + v1.x;
                float s1 = acc[mt][nt][h2 * 2 + 1] + v0.y + v1.y;
                float2 o;
                if (is_tanh) {
                    o.x = tanhf(s0); o.y = tanhf(s1);
                } else {
                    o.x = 1.0f / (1.0f + __expf(-s0));
                    o.y = 1.0f / (1.0f + __expf(-s1));
                }
                *(float2*)(dst + idx) = o;
            }
        }
}

// ---------------- Conversion kernels ----------------------------------------
__global__ void __launch_bounds__(256)
convL(B8 p)
{
    const int g = blockIdx.z;
    const size_t i = (size_t)blockIdx.x * 256 + threadIdx.x;   // float4 index
    float4 v = ((const float4*)p.b[g])[i];
    __nv_bfloat162 h01 = __floats2bfloat162_rn(v.x, v.y);
    __nv_bfloat162 h23 = __floats2bfloat162_rn(v.z, v.w);
    float4 lo;
    lo.x = v.x - __bfloat162float(__low2bfloat16(h01));
    lo.y = v.y - __bfloat162float(__high2bfloat16(h01));
    lo.z = v.z - __bfloat162float(__low2bfloat16(h23));
    lo.w = v.w - __bfloat162float(__high2bfloat16(h23));
    __nv_bfloat162 l01 = __floats2bfloat162_rn(lo.x, lo.y);
    __nv_bfloat162 l23 = __floats2bfloat162_rn(lo.z, lo.w);
    uint2 hv = make_uint2(*(uint32_t*)&h01, *(uint32_t*)&h23);
    uint2 lv = make_uint2(*(uint32_t*)&l01, *(uint32_t*)&l23);
    ((uint2*)(g_Lh + ((size_t)g << 20)))[i] = hv;
    ((uint2*)(g_Ll + ((size_t)g << 20)))[i] = lv;
}

struct P10 { const float* p[10]; };

__global__ void __launch_bounds__(256)
convT(P10 pp)
{
    __shared__ float t[32][33];
    const int z = blockIdx.z;
    const float* __restrict__ src = pp.p[z];
    __nv_bfloat16 *dh, *dl;
    if (z < 2) { dh = g_XTh + ((size_t)z << 20);       dl = g_XTl + ((size_t)z << 20); }
    else       { dh = g_RTh + ((size_t)(z - 2) << 20); dl = g_RTl + ((size_t)(z - 2) << 20); }

    const int tx = threadIdx.x & 31, ty = threadIdx.x >> 5;
    const int bx = blockIdx.x * 32, by = blockIdx.y * 32;
    #pragma unroll
    for (int j = 0; j < 4; j++)
        t[ty + j * 8][tx] = src[(size_t)(by + ty + j * 8) * NSZ + bx + tx];
    __syncthreads();
    #pragma unroll
    for (int j = 0; j < 4; j++) {
        float v = t[tx][ty + j * 8];
        __nv_bfloat16 h = __float2bfloat16_rn(v);
        __nv_bfloat16 l = __float2bfloat16_rn(v - __bfloat162float(h));
        const size_t o = (size_t)(bx + ty + j * 8) * NSZ + by + tx;
        dh[o] = h;
        dl[o] = l;
    }
}

// ---------------- Elementwise cell -------------------------------------------
__global__ void __launch_bounds__(256)
cellC(const float* __restrict__ c, float* __restrict__ out)
{
    const int idx = blockIdx.x * 256 + threadIdx.x;
    const float4* Gi = (const float4*)g_G;
    const float4* Gf = (const float4*)(g_G + (1ul << 20));
    const float4* Gg = (const float4*)(g_G + (2ul << 20));
    const float4* Go = (const float4*)(g_G + (3ul << 20));
    float4 vi = Gi[idx], vf = Gf[idx], vg = Gg[idx], vo = Go[idx];
    float4 vc = ((const float4*)c)[idx];
    float4 cn, hn;
    cn.x = vf.x * vc.x + vi.x * vg.x;
    cn.y = vf.y * vc.y + vi.y * vg.y;
    cn.z = vf.z * vc.z + vi.z * vg.z;
    cn.w = vf.w * vc.w + vi.w * vg.w;
    hn.x = vo.x * tanhf(cn.x);
    hn.y = vo.y * tanhf(cn.y);
    hn.z = vo.z * tanhf(cn.z);
    hn.w = vo.w * tanhf(cn.w);
    ((float4*)out)[idx] = hn;
    ((float4*)(out + (1ul << 20)))[idx] = cn;
}

// ---------------- launch -----------------------------------------------------
extern "C" void kernel_launch(void* const* d_in, const int* in_sizes, int n_in,
                              void* d_out, int out_size)
{
    (void)in_sizes; (void)n_in; (void)out_size;
    const float* x = (const float*)d_in[0];
    const float* h = (const float*)d_in[1];
    const float* c = (const float*)d_in[2];

    B8 pL, pB;
    P10 pT;
    pT.p[0] = x;
    pT.p[1] = h;
    for (int g = 0; g < 8; g++) {
        pL.b[g]     = (const float*)d_in[3 + 3 * g];   // L_g
        pT.p[2 + g] = (const float*)d_in[4 + 3 * g];   // R_g (transposed)
        pB.b[g]     = (const float*)d_in[5 + 3 * g];   // b_g
    }

    cudaFuncSetAttribute(gemm1, cudaFuncAttributeMaxDynamicSharedMemorySize, SMEM_TOTAL);
    cudaFuncSetAttribute(gemm2, cudaFuncAttributeMaxDynamicSharedMemorySize, SMEM_TOTAL);

    convL<<<dim3(1024, 1, 8), 256>>>(pL);
    convT<<<dim3(32, 32, 10), 256>>>(pT);
    gemm1<<<dim3(8, 8, 8), 256, SMEM_TOTAL>>>();
    gemm2<<<dim3(8, 8, 4), 256, SMEM_TOTAL>>>(pB);
    cellC<<<dim3(1024), 256>>>(c, (float*)d_out);
}

// round 8
// speedup vs baseline: 3.4603x; 1.3105x over previous
#include <cuda_runtime.h>
#include <cuda_fp16.h>
#include <cstdint>
#include <math.h>

#define NSZ 1024

// ---------------- scratch (static device globals; no runtime alloc) --------
__device__ __align__(16) __half g_Lh[8u << 20];
__device__ __align__(16) __half g_Ll[8u << 20];
__device__ __align__(16) __half g_XTh[2u << 20];
__device__ __align__(16) __half g_RTh[8u << 20];
__device__ __align__(16) __half g_Ph[8u << 20];
__device__ __align__(16) __half g_Pl[8u << 20];
__device__ __align__(16) float g_G[4u << 20];

// ---------------- SMEM stage layout ----------------------------------------
#define OFF_AL 8192
#define OFF_BH 16384
#define STAGE_BYTES 24576
#define NSTAGES 4
#define MBAR_OFF (NSTAGES * STAGE_BYTES)          // 98304
#define SMEM_TOTAL (MBAR_OFF + 64)

// ---------------- PTX helpers (all baseline sm_80/90-level) -----------------
__device__ __forceinline__ uint32_t smem_u32(const void* p) {
    uint32_t a;
    asm("{ .reg .u64 t; cvta.to.shared.u64 t, %1; cvt.u32.u64 %0, t; }"
        : "=r"(a) : "l"(p));
    return a;
}
__device__ __forceinline__ void cp16(uint32_t smem, const void* g) {
    asm volatile("cp.async.cg.shared.global [%0], [%1], 16;"
                 :: "r"(smem), "l"(g));
}
__device__ __forceinline__ void mbar_init(uint32_t a, uint32_t cnt) {
    asm volatile("mbarrier.init.shared.b64 [%0], %1;" :: "r"(a), "r"(cnt) : "memory");
}
__device__ __forceinline__ void mbar_arrive(uint32_t a) {
    asm volatile("mbarrier.arrive.shared.b64 _, [%0];" :: "r"(a) : "memory");
}
// .noinc: one async arrive per thread when its prior cp.asyncs complete.
__device__ __forceinline__ void cp_mbar_arrive(uint32_t a) {
    asm volatile("cp.async.mbarrier.arrive.noinc.shared.b64 [%0];" :: "r"(a) : "memory");
}
__device__ __forceinline__ void mbar_wait(uint32_t a, uint32_t phase) {
    asm volatile("{\n\t.reg .pred P;\n\tWL%=:\n\t"
                 "mbarrier.try_wait.parity.acquire.cta.shared::cta.b64 P, [%0], %1, 0x989680;\n\t"
                 "@!P bra WL%=;\n\t}" :: "r"(a), "r"(phase) : "memory");
}
__device__ __forceinline__ void ldsm_x4(uint32_t (&r)[4], uint32_t addr) {
    asm volatile("ldmatrix.sync.aligned.m8n8.x4.shared.b16 {%0,%1,%2,%3}, [%4];"
                 : "=r"(r[0]), "=r"(r[1]), "=r"(r[2]), "=r"(r[3]) : "r"(addr));
}
__device__ __forceinline__ void mma16816(float (&d)[4], const uint32_t (&a)[4],
                                         uint32_t b0, uint32_t b1) {
    asm volatile("mma.sync.aligned.m16n8k16.row.col.f32.f16.f16.f32 "
                 "{%0,%1,%2,%3}, {%4,%5,%6,%7}, {%8,%9}, {%0,%1,%2,%3};"
                 : "+f"(d[0]), "+f"(d[1]), "+f"(d[2]), "+f"(d[3])
                 : "r"(a[0]), "r"(a[1]), "r"(a[2]), "r"(a[3]), "r"(b0), "r"(b1));
}

// swizzle: 16B chunk j within 64B row r -> j ^ ((r>>1)&3)
__device__ __forceinline__ uint32_t sw_off(int r, int j) {
    return (uint32_t)(r * 64 + ((j ^ ((r >> 1) & 3)) << 4));
}

// load one [128 rows x 32 k] fp16 tile into swizzled SMEM via cp.async
__device__ __forceinline__ void issue_mat(const __half* __restrict__ src,
                                          int row0, int k0, uint32_t dst, int tid) {
    #pragma unroll
    for (int i = 0; i < 2; i++) {
        int f = tid + i * 256;
        int r = f >> 2;
        int j = f & 3;
        cp16(dst + sw_off(r, j), src + (size_t)(row0 + r) * NSZ + k0 + j * 8);
    }
}

__device__ __forceinline__ void issue_stage(uint32_t sb, int buf,
    const __half* Ah, const __half* Al, const __half* Bh,
    int rowTile, int colTile, int k0, int tid)
{
    uint32_t base = sb + buf * STAGE_BYTES;
    issue_mat(Ah, rowTile, k0, base,          tid);
    issue_mat(Al, rowTile, k0, base + OFF_AL, tid);
    issue_mat(Bh, colTile, k0, base + OFF_BH, tid);
}

// ---------------- split-fp16 GEMM mainloop (mbarrier ring, depth 4) ---------
// acc += (Ah + Al) @ Bh     (drops A@Bl term: ~2.8e-4 relative)
__device__ __forceinline__ void mainloop(
    uint32_t sb, int tid, int nhalf,
    const __half* const* Ah, const __half* const* Al, const __half* const* Bh,
    int rowTile, int colTile, float (&acc)[4][4][4])
{
    const int lane = tid & 31;
    const int wid  = tid >> 5;
    const int wm   = wid >> 2;       // 0..1  (64 rows)
    const int wn   = wid & 3;        // 0..3  (32 cols)

    const uint32_t fullB  = sb + MBAR_OFF;        // full[b]  = +b*8
    const uint32_t emptyB = sb + MBAR_OFF + 32;   // empty[b] = +b*8

    if (tid == 0) {
        #pragma unroll
        for (int b = 0; b < NSTAGES; b++) {
            mbar_init(fullB  + b * 8, 256);
            mbar_init(emptyB + b * 8, 256);
        }
    }
    __syncthreads();   // inits visible before any arrive

    // precompute ldmatrix lane offsets (relative to stage base)
    uint32_t aOff[2][4], bOff[2][2];
    #pragma unroll
    for (int ks = 0; ks < 2; ks++) {
        #pragma unroll
        for (int mt = 0; mt < 4; mt++) {
            int r = wm * 64 + mt * 16 + (lane & 15);
            int j = ks * 2 + (lane >> 4);
            aOff[ks][mt] = sw_off(r, j);
        }
        #pragma unroll
        for (int bp = 0; bp < 2; bp++) {
            int r = wn * 32 + bp * 16 + ((lane >> 4) * 8) + (lane & 7);
            int j = ks * 2 + ((lane >> 3) & 1);
            bOff[ks][bp] = OFF_BH + sw_off(r, j);
        }
    }

    const int NS = 32 * nhalf;

    // prologue: fill all 4 buffers (stages 0..3, all within half 0)
    #pragma unroll
    for (int s = 0; s < NSTAGES; s++) {
        issue_stage(sb, s, Ah[0], Al[0], Bh[0], rowTile, colTile, s * 32, tid);
        cp_mbar_arrive(fullB + s * 8);
    }

    uint32_t fmask = 0, emask = 0;
    int b = 0;
    #pragma unroll 1
    for (int s = 0; s < NS; s++) {
        // wait buffer full (acquire: makes peers' cp.async data visible)
        mbar_wait(fullB + b * 8, (fmask >> b) & 1);
        fmask ^= 1u << b;

        const uint32_t base = sb + b * STAGE_BYTES;
        #pragma unroll
        for (int ks = 0; ks < 2; ks++) {
            uint32_t Af[4][4], Lf[4][4], Bf[2][4];
            #pragma unroll
            for (int mt = 0; mt < 4; mt++) ldsm_x4(Af[mt], base + aOff[ks][mt]);
            #pragma unroll
            for (int mt = 0; mt < 4; mt++) ldsm_x4(Lf[mt], base + OFF_AL + aOff[ks][mt]);
            #pragma unroll
            for (int bp = 0; bp < 2; bp++) ldsm_x4(Bf[bp], base + bOff[ks][bp]);
            if (ks == 1) mbar_arrive(emptyB + b * 8);   // all my reads of buf b done

            // pass hh
            #pragma unroll
            for (int mt = 0; mt < 4; mt++)
                #pragma unroll
                for (int nt = 0; nt < 4; nt++)
                    mma16816(acc[mt][nt], Af[mt],
                             Bf[nt >> 1][(nt & 1) * 2], Bf[nt >> 1][(nt & 1) * 2 + 1]);
            // pass lh (A-lo x B-hi)
            #pragma unroll
            for (int mt = 0; mt < 4; mt++)
                #pragma unroll
                for (int nt = 0; nt < 4; nt++)
                    mma16816(acc[mt][nt], Lf[mt],
                             Bf[nt >> 1][(nt & 1) * 2], Bf[nt >> 1][(nt & 1) * 2 + 1]);
        }

        // refill this buffer for stage s+4 (after my LDSMs; peers done by now)
        const int sn = s + NSTAGES;
        if (sn < NS) {
            mbar_wait(emptyB + b * 8, (emask >> b) & 1);
            emask ^= 1u << b;
            const int hf = sn >> 5;
            issue_stage(sb, b, Ah[hf], Al[hf], Bh[hf],
                        rowTile, colTile, (sn & 31) * 32, tid);
            cp_mbar_arrive(fullB + b * 8);
        }
        b = (b + 1) & 3;
    }
}

// ---------------- Kernel: phase 1  P_g = L_g @ X_g --------------------------
__global__ void __launch_bounds__(256, 2)
gemm1()
{
    extern __shared__ char smem[];
    const uint32_t sb = smem_u32(smem);
    const int tid = threadIdx.x;
    const int gate = blockIdx.z;
    const int rowTile = blockIdx.y * 128, colTile = blockIdx.x * 128;

    float acc[4][4][4];
    #pragma unroll
    for (int a = 0; a < 4; a++)
        #pragma unroll
        for (int b = 0; b < 4; b++)
            #pragma unroll
            for (int e = 0; e < 4; e++) acc[a][b][e] = 0.0f;

    const __half* Ah[2] = { g_Lh  + ((size_t)gate << 20), nullptr };
    const __half* Al[2] = { g_Ll  + ((size_t)gate << 20), nullptr };
    const __half* Bh[2] = { g_XTh + ((size_t)(gate & 1) << 20), nullptr };

    mainloop(sb, tid, 1, Ah, Al, Bh, rowTile, colTile, acc);

    // epilogue: split P into fp16 hi/lo
    const int lane = tid & 31, wid = tid >> 5;
    const int wm = wid >> 2, wn = wid & 3;
    __half* dh = g_Ph + ((size_t)gate << 20);
    __half* dl = g_Pl + ((size_t)gate << 20);
    const int m0 = rowTile + wm * 64 + (lane >> 2);
    const int n0 = colTile + wn * 32 + (lane & 3) * 2;
    #pragma unroll
    for (int mt = 0; mt < 4; mt++)
        #pragma unroll
        for (int h2 = 0; h2 < 2; h2++) {
            const int m = m0 + mt * 16 + h2 * 8;
            const size_t rowb = (size_t)m * NSZ;
            #pragma unroll
            for (int nt = 0; nt < 4; nt++) {
                float v0 = acc[mt][nt][h2 * 2 + 0];
                float v1 = acc[mt][nt][h2 * 2 + 1];
                __half h0 = __float2half_rn(v0);
                __half h1 = __float2half_rn(v1);
                __half l0 = __float2half_rn(v0 - __half2float(h0));
                __half l1 = __float2half_rn(v1 - __half2float(h1));
                __half2 hp = __halves2half2(h0, h1);
                __half2 lp = __halves2half2(l0, l1);
                *(uint32_t*)(dh + rowb + n0 + nt * 8) = *(uint32_t*)&hp;
                *(uint32_t*)(dl + rowb + n0 + nt * 8) = *(uint32_t*)&lp;
            }
        }
}

// ---------------- Kernel: phase 2  gates = act(P@R pair + biases) ----------
struct B8 { const float* b[8]; };

__global__ void __launch_bounds__(256, 2)
gemm2(B8 pb)
{
    extern __shared__ char smem[];
    const uint32_t sb = smem_u32(smem);
    const int tid = threadIdx.x;
    const int pr = blockIdx.z;                 // 0:i 1:f 2:g 3:o
    const int g0 = 2 * pr;
    const int rowTile = blockIdx.y * 128, colTile = blockIdx.x * 128;

    float acc[4][4][4];
    #pragma unroll
    for (int a = 0; a < 4; a++)
        #pragma unroll
        for (int b = 0; b < 4; b++)
            #pragma unroll
            for (int e = 0; e < 4; e++) acc[a][b][e] = 0.0f;

    const __half* Ah[2] = { g_Ph  + ((size_t)g0 << 20), g_Ph  + ((size_t)(g0 + 1) << 20) };
    const __half* Al[2] = { g_Pl  + ((size_t)g0 << 20), g_Pl  + ((size_t)(g0 + 1) << 20) };
    const __half* Bh[2] = { g_RTh + ((size_t)g0 << 20), g_RTh + ((size_t)(g0 + 1) << 20) };

    mainloop(sb, tid, 2, Ah, Al, Bh, rowTile, colTile, acc);

    // epilogue: + b0 + b1, activation, store fp32 gate
    const int lane = tid & 31, wid = tid >> 5;
    const int wm = wid >> 2, wn = wid & 3;
    const float* __restrict__ b0 = pb.b[g0];
    const float* __restrict__ b1 = pb.b[g0 + 1];
    float* dst = g_G + ((size_t)pr << 20);
    const bool is_tanh = (pr == 2);
    const int m0 = rowTile + wm * 64 + (lane >> 2);
    const int n0 = colTile + wn * 32 + (lane & 3) * 2;
    #pragma unroll
    for (int mt = 0; mt < 4; mt++)
        #pragma unroll
        for (int h2 = 0; h2 < 2; h2++) {
            const int m = m0 + mt * 16 + h2 * 8;
            const size_t rowb = (size_t)m * NSZ;
            #pragma unroll
            for (int nt = 0; nt < 4; nt++) {
                const size_t idx = rowb + n0 + nt * 8;
                float2 v0 = *(const float2*)(b0 + idx);
                float2 v1 = *(const float2*)(b1 + idx);
                float s0 = acc[mt][nt][h2 * 2 + 0] + v0.x + v1.x;
                float s1 = acc[mt][nt][h2 * 2 + 1] + v0.y + v1.y;
                float2 o;
                if (is_tanh) {
                    o.x = tanhf(s0); o.y = tanhf(s1);
                } else {
                    o.x = 1.0f / (1.0f + __expf(-s0));
                    o.y = 1.0f / (1.0f + __expf(-s1));
                }
                *(float2*)(dst + idx) = o;
            }
        }
}

// ---------------- Conversion kernels ----------------------------------------
__global__ void __launch_bounds__(256)
convL(B8 p)
{
    const int g = blockIdx.z;
    const size_t i = (size_t)blockIdx.x * 256 + threadIdx.x;   // float4 index
    float4 v = ((const float4*)p.b[g])[i];
    __half h0 = __float2half_rn(v.x), h1 = __float2half_rn(v.y);
    __half h2 = __float2half_rn(v.z), h3 = __float2half_rn(v.w);
    __half l0 = __float2half_rn(v.x - __half2float(h0));
    __half l1 = __float2half_rn(v.y - __half2float(h1));
    __half l2 = __float2half_rn(v.z - __half2float(h2));
    __half l3 = __float2half_rn(v.w - __half2float(h3));
    __half2 hA = __halves2half2(h0, h1), hB = __halves2half2(h2, h3);
    __half2 lA = __halves2half2(l0, l1), lB = __halves2half2(l2, l3);
    ((uint2*)(g_Lh + ((size_t)g << 20)))[i] = make_uint2(*(uint32_t*)&hA, *(uint32_t*)&hB);
    ((uint2*)(g_Ll + ((size_t)g << 20)))[i] = make_uint2(*(uint32_t*)&lA, *(uint32_t*)&lB);
}

struct P10 { const float* p[10]; };

__global__ void __launch_bounds__(256)
convT(P10 pp)
{
    __shared__ float t[32][33];
    const int z = blockIdx.z;
    const float* __restrict__ src = pp.p[z];
    __half* dh;
    if (z < 2) dh = g_XTh + ((size_t)z << 20);
    else       dh = g_RTh + ((size_t)(z - 2) << 20);

    const int tx = threadIdx.x & 31, ty = threadIdx.x >> 5;
    const int bx = blockIdx.x * 32, by = blockIdx.y * 32;
    #pragma unroll
    for (int j = 0; j < 4; j++)
        t[ty + j * 8][tx] = src[(size_t)(by + ty + j * 8) * NSZ + bx + tx];
    __syncthreads();
    #pragma unroll
    for (int j = 0; j < 4; j++) {
        float v = t[tx][ty + j * 8];
        dh[(size_t)(bx + ty + j * 8) * NSZ + by + tx] = __float2half_rn(v);
    }
}

// ---------------- Elementwise cell -------------------------------------------
__global__ void __launch_bounds__(256)
cellC(const float* __restrict__ c, float* __restrict__ out)
{
    const int idx = blockIdx.x * 256 + threadIdx.x;
    const float4* Gi = (const float4*)g_G;
    const float4* Gf = (const float4*)(g_G + (1ul << 20));
    const float4* Gg = (const float4*)(g_G + (2ul << 20));
    const float4* Go = (const float4*)(g_G + (3ul << 20));
    float4 vi = Gi[idx], vf = Gf[idx], vg = Gg[idx], vo = Go[idx];
    float4 vc = ((const float4*)c)[idx];
    float4 cn, hn;
    cn.x = vf.x * vc.x + vi.x * vg.x;
    cn.y = vf.y * vc.y + vi.y * vg.y;
    cn.z = vf.z * vc.z + vi.z * vg.z;
    cn.w = vf.w * vc.w + vi.w * vg.w;
    hn.x = vo.x * tanhf(cn.x);
    hn.y = vo.y * tanhf(cn.y);
    hn.z = vo.z * tanhf(cn.z);
    hn.w = vo.w * tanhf(cn.w);
    ((float4*)out)[idx] = hn;
    ((float4*)(out + (1ul << 20)))[idx] = cn;
}

// ---------------- launch -----------------------------------------------------
extern "C" void kernel_launch(void* const* d_in, const int* in_sizes, int n_in,
                              void* d_out, int out_size)
{
    (void)in_sizes; (void)n_in; (void)out_size;
    const float* x = (const float*)d_in[0];
    const float* h = (const float*)d_in[1];
    const float* c = (const float*)d_in[2];

    B8 pL, pB;
    P10 pT;
    pT.p[0] = x;
    pT.p[1] = h;
    for (int g = 0; g < 8; g++) {
        pL.b[g]     = (const float*)d_in[3 + 3 * g];   // L_g
        pT.p[2 + g] = (const float*)d_in[4 + 3 * g];   // R_g (transposed)
        pB.b[g]     = (const float*)d_in[5 + 3 * g];   // b_g
    }

    cudaFuncSetAttribute(gemm1, cudaFuncAttributeMaxDynamicSharedMemorySize, SMEM_TOTAL);
    cudaFuncSetAttribute(gemm2, cudaFuncAttributeMaxDynamicSharedMemorySize, SMEM_TOTAL);

    convL<<<dim3(1024, 1, 8), 256>>>(pL);
    convT<<<dim3(32, 32, 10), 256>>>(pT);
    gemm1<<<dim3(8, 8, 8), 256, SMEM_TOTAL>>>();
    gemm2<<<dim3(8, 8, 4), 256, SMEM_TOTAL>>>(pB);
    cellC<<<dim3(1024), 256>>>(c, (float*)d_out);
}